// round 7
// baseline (speedup 1.0000x reference)
#include <cuda_runtime.h>
#include <cuda_bf16.h>

#define N_NODES 100000
#define N_EDGES 3200000
#define IN_CH 128
#define HID 30
#define HPAD 32

// Scratch (allocation-free): y = projected features, agg = self + neighbor sums
__device__ float g_y[N_NODES * HPAD];
__device__ float g_agg[N_NODES * HPAD];
__device__ int g_idx64;  // 1 if edge_index is int64, 0 if int32

// ---------------------------------------------------------------------------
// Kernel 0: detect edge_index width. If int64 with values < 2^31, the high
// 32-bit word of every entry is 0. If int32, those words are independent
// random node indices — 2048 samples all zero has probability ~0.
// Samples are strided across the whole src array.
// ---------------------------------------------------------------------------
__global__ void gin_detect_idx(const int* __restrict__ ei32) {
    __shared__ int all_zero;
    if (threadIdx.x == 0) all_zero = 1;
    __syncthreads();
    const int STRIDE = N_EDGES / 2048;  // 1562
    for (int i = threadIdx.x; i < 2048; i += blockDim.x) {
        int e = i * STRIDE;
        if (ei32[2 * e + 1] != 0) all_zero = 0;  // benign race: all writes are 0
    }
    __syncthreads();
    if (threadIdx.x == 0) g_idx64 = all_zero;
}

// ---------------------------------------------------------------------------
// Kernel 1: y = x @ w1a  (N x 128 -> N x 30, padded to 32), agg initialized = y
// ---------------------------------------------------------------------------
__global__ void gin_proj1(const float* __restrict__ x, const float* __restrict__ w) {
    __shared__ float ws[2048];  // one 64-row chunk of w (64 x 30 = 1920 floats)

    int node = blockIdx.x * blockDim.x + threadIdx.x;

    float acc[HID];
#pragma unroll
    for (int c = 0; c < HID; c++) acc[c] = 0.f;

    const float4* xr = reinterpret_cast<const float4*>(x + (size_t)node * IN_CH);

    for (int kc = 0; kc < 2; kc++) {  // two chunks of 64 input channels
        __syncthreads();
        for (int i = threadIdx.x; i < 64 * HID; i += blockDim.x)
            ws[i] = w[kc * 64 * HID + i];
        __syncthreads();

        if (node < N_NODES) {
            for (int k4 = 0; k4 < 16; k4++) {
                float4 xv = xr[kc * 16 + k4];
                int k = k4 * 4;
#pragma unroll
                for (int c = 0; c < HID; c++) {
                    acc[c] += xv.x * ws[(k + 0) * HID + c];
                    acc[c] += xv.y * ws[(k + 1) * HID + c];
                    acc[c] += xv.z * ws[(k + 2) * HID + c];
                    acc[c] += xv.w * ws[(k + 3) * HID + c];
                }
            }
        }
    }

    if (node >= N_NODES) return;

    float4* yo = reinterpret_cast<float4*>(g_y + (size_t)node * HPAD);
    float4* ao = reinterpret_cast<float4*>(g_agg + (size_t)node * HPAD);
#pragma unroll
    for (int q = 0; q < 8; q++) {
        float4 v;
        v.x = (q * 4 + 0 < HID) ? acc[q * 4 + 0] : 0.f;
        v.y = (q * 4 + 1 < HID) ? acc[q * 4 + 1] : 0.f;
        v.z = (q * 4 + 2 < HID) ? acc[q * 4 + 2] : 0.f;
        v.w = (q * 4 + 3 < HID) ? acc[q * 4 + 3] : 0.f;
        yo[q] = v;
        ao[q] = v;
    }
}

// ---------------------------------------------------------------------------
// Kernel 2: edge scatter. 8 threads per edge; each thread handles one float4
// (4 channels). agg[dst] += y[src] via vectorized red.global.add.v4.f32.
// Index width selected at runtime via g_idx64 (uniform branch, no divergence).
// ---------------------------------------------------------------------------
__global__ void gin_scatter(const void* __restrict__ ei_raw) {
    long long t = (long long)blockIdx.x * blockDim.x + threadIdx.x;
    if (t >= (long long)N_EDGES * 8) return;
    int e = (int)(t >> 3);
    int q = (int)(t & 7);

    int s, d;
    if (g_idx64) {
        const long long* ei = (const long long*)ei_raw;
        s = (int)__ldg(ei + e);
        d = (int)__ldg(ei + N_EDGES + e);
    } else {
        const int* ei = (const int*)ei_raw;
        s = __ldg(ei + e);
        d = __ldg(ei + N_EDGES + e);
    }

    const float4* yp = reinterpret_cast<const float4*>(g_y + (size_t)s * HPAD + q * 4);
    float4 v = __ldg(yp);
    float* a = g_agg + (size_t)d * HPAD + q * 4;
    asm volatile("red.global.add.v4.f32 [%0], {%1,%2,%3,%4};"
                 :: "l"(a), "f"(v.x), "f"(v.y), "f"(v.z), "f"(v.w)
                 : "memory");
}

// ---------------------------------------------------------------------------
// Kernel 3: fused node update between layers.
//   t = relu(agg + ba); z = t @ wb + bb; h = relu(z); y_next = h @ wa_next
//   writes y_next into g_y and g_agg (self-term init for next scatter).
// ---------------------------------------------------------------------------
__global__ void gin_fused(const float* __restrict__ ba, const float* __restrict__ wb,
                          const float* __restrict__ bb, const float* __restrict__ wan) {
    __shared__ float swb[HID * HID];
    __shared__ float swan[HID * HID];
    __shared__ float sba[HID];
    __shared__ float sbb[HID];
    for (int i = threadIdx.x; i < HID * HID; i += blockDim.x) {
        swb[i] = wb[i];
        swan[i] = wan[i];
    }
    if (threadIdx.x < HID) { sba[threadIdx.x] = ba[threadIdx.x]; sbb[threadIdx.x] = bb[threadIdx.x]; }
    __syncthreads();

    int node = blockIdx.x * blockDim.x + threadIdx.x;
    if (node >= N_NODES) return;

    float av[HPAD];
    const float4* ar = reinterpret_cast<const float4*>(g_agg + (size_t)node * HPAD);
#pragma unroll
    for (int q = 0; q < 8; q++) {
        float4 v = ar[q];
        av[q * 4 + 0] = v.x; av[q * 4 + 1] = v.y; av[q * 4 + 2] = v.z; av[q * 4 + 3] = v.w;
    }

    float tt[HID];
#pragma unroll
    for (int c = 0; c < HID; c++) tt[c] = fmaxf(av[c] + sba[c], 0.f);

    float hh[HID];
#pragma unroll
    for (int c = 0; c < HID; c++) {
        float z = sbb[c];
#pragma unroll
        for (int k = 0; k < HID; k++) z += tt[k] * swb[k * HID + c];
        hh[c] = fmaxf(z, 0.f);
    }

    float yy[HID];
#pragma unroll
    for (int c = 0; c < HID; c++) {
        float z = 0.f;
#pragma unroll
        for (int k = 0; k < HID; k++) z += hh[k] * swan[k * HID + c];
        yy[c] = z;
    }

    float4* yo = reinterpret_cast<float4*>(g_y + (size_t)node * HPAD);
    float4* ao = reinterpret_cast<float4*>(g_agg + (size_t)node * HPAD);
#pragma unroll
    for (int q = 0; q < 8; q++) {
        float4 v;
        v.x = (q * 4 + 0 < HID) ? yy[q * 4 + 0] : 0.f;
        v.y = (q * 4 + 1 < HID) ? yy[q * 4 + 1] : 0.f;
        v.z = (q * 4 + 2 < HID) ? yy[q * 4 + 2] : 0.f;
        v.w = (q * 4 + 3 < HID) ? yy[q * 4 + 3] : 0.f;
        yo[q] = v;
        ao[q] = v;
    }
}

// ---------------------------------------------------------------------------
// Kernel 4: final layer + log_softmax.
//   t = relu(agg + b3a); z = t @ w3b + b3b; h = relu(z); out = log_softmax(h)
// ---------------------------------------------------------------------------
__global__ void gin_final(const float* __restrict__ ba, const float* __restrict__ wb,
                          const float* __restrict__ bb, float* __restrict__ out) {
    __shared__ float swb[HID * HID];
    __shared__ float sba[HID];
    __shared__ float sbb[HID];
    for (int i = threadIdx.x; i < HID * HID; i += blockDim.x) swb[i] = wb[i];
    if (threadIdx.x < HID) { sba[threadIdx.x] = ba[threadIdx.x]; sbb[threadIdx.x] = bb[threadIdx.x]; }
    __syncthreads();

    int node = blockIdx.x * blockDim.x + threadIdx.x;
    if (node >= N_NODES) return;

    float av[HPAD];
    const float4* ar = reinterpret_cast<const float4*>(g_agg + (size_t)node * HPAD);
#pragma unroll
    for (int q = 0; q < 8; q++) {
        float4 v = ar[q];
        av[q * 4 + 0] = v.x; av[q * 4 + 1] = v.y; av[q * 4 + 2] = v.z; av[q * 4 + 3] = v.w;
    }

    float tt[HID];
#pragma unroll
    for (int c = 0; c < HID; c++) tt[c] = fmaxf(av[c] + sba[c], 0.f);

    float hh[HID];
    float m = -1e30f;
#pragma unroll
    for (int c = 0; c < HID; c++) {
        float z = sbb[c];
#pragma unroll
        for (int k = 0; k < HID; k++) z += tt[k] * swb[k * HID + c];
        hh[c] = fmaxf(z, 0.f);   // outer relu
        m = fmaxf(m, hh[c]);
    }

    float ssum = 0.f;
#pragma unroll
    for (int c = 0; c < HID; c++) ssum += __expf(hh[c] - m);
    float ls = m + logf(ssum);

    float* o = out + (size_t)node * HID;
#pragma unroll
    for (int c = 0; c < HID; c++) o[c] = hh[c] - ls;
}

// ---------------------------------------------------------------------------
extern "C" void kernel_launch(void* const* d_in, const int* in_sizes, int n_in,
                              void* d_out, int out_size) {
    const float* x   = (const float*)d_in[0];
    const void*  ei  = d_in[1];
    const float* w1a = (const float*)d_in[2];
    const float* b1a = (const float*)d_in[3];
    const float* w1b = (const float*)d_in[4];
    const float* b1b = (const float*)d_in[5];
    const float* w2a = (const float*)d_in[6];
    const float* b2a = (const float*)d_in[7];
    const float* w2b = (const float*)d_in[8];
    const float* b2b = (const float*)d_in[9];
    const float* w3a = (const float*)d_in[10];
    const float* b3a = (const float*)d_in[11];
    const float* w3b = (const float*)d_in[12];
    const float* b3b = (const float*)d_in[13];
    float* out = (float*)d_out;

    const int NB_NODE = (N_NODES + 127) / 128;
    const long long total_sc = (long long)N_EDGES * 8;
    const int NB_SC = (int)((total_sc + 511) / 512);

    gin_detect_idx<<<1, 256>>>((const int*)ei);
    // Layer 1
    gin_proj1<<<(N_NODES + 127) / 128, 128>>>(x, w1a);
    gin_scatter<<<NB_SC, 512>>>(ei);
    gin_fused<<<NB_NODE, 128>>>(b1a, w1b, b1b, w2a);
    // Layer 2
    gin_scatter<<<NB_SC, 512>>>(ei);
    gin_fused<<<NB_NODE, 128>>>(b2a, w2b, b2b, w3a);
    // Layer 3
    gin_scatter<<<NB_SC, 512>>>(ei);
    gin_final<<<NB_NODE, 128>>>(b3a, w3b, b3b, out);

    (void)in_sizes; (void)n_in; (void)out_size;
}